// round 7
// baseline (speedup 1.0000x reference)
#include <cuda_runtime.h>

// WLC loss: fused 5-iter morphological recurrence, register-resident pred.
// NT=256 (8 warps), 3 CTAs/SM (85 regs/thread). Warp = 128-px row band,
// thread owns R=8 rows x 4 cols in registers across all iterations.
// Horizontal neighbors via shfl; vertical warp-strip coupling via small
// double-buffered smem edge rows. pred loaded gmem->regs directly.

#define IMG    4096
#define NT     256
#define WARPS  8
#define R      8
#define EXTX   128
#define TSX    118
#define EXTY   (WARPS * R + 2)     // 66
#define TSY    (EXTY - 10)         // 56
#define GRIDX  35                  // ceil(4096/118)
#define GRIDY  74                  // ceil(4096/56)
#define NBLK   (GRIDX * GRIDY)     // 2590
#define CLO    5
#define CHIX   123                 // useful cols [5,123)
#define CHIY   (EXTY - 5)          // useful rows [5,61)

#define GTN    (EXTY * EXTX)           // 8448 floats (gt/2)
#define ETSLOT (WARPS + 1)
#define ETN    (2 * ETSLOT * EXTX)     // 2304
#define EBN    (2 * WARPS * EXTX)      // 2048
#define SMEMB  ((GTN + ETN + EBN) * 4) // 51200 B

__device__ float    g_acc[2];   // zero-init; self-resets every launch
__device__ unsigned g_done;

__device__ __forceinline__ float tanha(float x) {
    float y; asm("tanh.approx.f32 %0, %1;" : "=f"(y) : "f"(x)); return y;
}
__device__ __forceinline__ float4 ld4(const float* p) {
    return *reinterpret_cast<const float4*>(p);
}
__device__ __forceinline__ void st4(float* p, float4 v) {
    *reinterpret_cast<float4*>(p) = v;
}

// horizontal 3-sums; lane-boundary garbage lands only in the halo-creep zone
__device__ __forceinline__ float4 hsum(float4 c) {
    float l = __shfl_up_sync(0xffffffffu, c.w, 1);
    float r = __shfl_down_sync(0xffffffffu, c.x, 1);
    float t1 = c.x + c.y;
    float t2 = c.z + c.w;
    float4 h;
    h.x = l + t1;
    h.y = t1 + c.z;
    h.z = c.y + t2;
    h.w = t2 + r;
    return h;
}

__device__ __forceinline__ float4 load_pred_row(
    const float* __restrict__ pred, int gy, int gxBase,
    bool c0, bool c1, bool c2, bool c3)
{
    float4 v = make_float4(0.f, 0.f, 0.f, 0.f);
    if ((unsigned)gy < (unsigned)IMG) {
        const float* p = pred + gy * IMG + gxBase;
        if (c0) v.x = __ldg(p + 0);
        if (c1) v.y = __ldg(p + 1);
        if (c2) v.z = __ldg(p + 2);
        if (c3) v.w = __ldg(p + 3);
    }
    return v;
}

__global__ __launch_bounds__(NT, 3)
void wlc_main(const float* __restrict__ pred, const float* __restrict__ gt,
              float* __restrict__ out)
{
    extern __shared__ float sm[];
    float* gtb = sm;             // gt/2 tile [EXTY][EXTX]
    float* eT  = sm + GTN;       // [2][WARPS+1][EXTX] top-edge sources
    float* eB  = eT + ETN;       // [2][WARPS][EXTX]   bottom-edge sources

    const int tid  = threadIdx.x;
    const int w    = tid >> 5;
    const int lane = tid & 31;
    const int col0 = 4 * lane;
    const int gx0  = blockIdx.x * TSX - 5;
    const int gy0  = blockIdx.y * TSY - 5;
    const int gxBase = gx0 + col0;

    const bool c0 = (unsigned)(gxBase + 0) < (unsigned)IMG;
    const bool c1 = (unsigned)(gxBase + 1) < (unsigned)IMG;
    const bool c2 = (unsigned)(gxBase + 2) < (unsigned)IMG;
    const bool c3 = (unsigned)(gxBase + 3) < (unsigned)IMG;

    // ---- pred directly into registers (high MLP, coalesced per warp) ----
    float4 c[R], cTop, cBot;
    cTop = load_pred_row(pred, gy0 + w * R,         gxBase, c0, c1, c2, c3);
    #pragma unroll
    for (int r = 0; r < R; ++r)
        c[r] = load_pred_row(pred, gy0 + 1 + w * R + r, gxBase, c0, c1, c2, c3);
    cBot = load_pred_row(pred, gy0 + 1 + (w + 1) * R,  gxBase, c0, c1, c2, c3);

    // ---- constant edge rows (row 0 / row EXTY-1 of pred_0), both parities ----
    {
        int j   = tid & 127;
        int row = (tid < 128) ? 0 : (EXTY - 1);
        int gy  = gy0 + row, gx = gx0 + j;
        float v = 0.f;
        if (((unsigned)gy < (unsigned)IMG) & ((unsigned)gx < (unsigned)IMG))
            v = __ldg(pred + gy * IMG + gx);
        if (tid < 128) {
            eT[0 * ETSLOT * EXTX + j] = v;
            eT[1 * ETSLOT * EXTX + j] = v;
        } else {
            eB[(0 * WARPS + WARPS - 1) * EXTX + j] = v;
            eB[(1 * WARPS + WARPS - 1) * EXTX + j] = v;
        }
    }

    // ---- gt: store gt/2 into smem, accumulate central gt sum ----
    float gtLocal = 0.f;
    #pragma unroll 1
    for (int i = tid; i < GTN; i += NT) {
        int r = i >> 7, cc = i & 127;
        int gy = gy0 + r, gx = gx0 + cc;
        float gv = 0.f;
        if (((unsigned)gy < (unsigned)IMG) & ((unsigned)gx < (unsigned)IMG))
            gv = __ldg(gt + gy * IMG + gx);
        gtb[i] = 0.5f * gv;
        if (r >= CLO && r < CHIY && cc >= CLO && cc < CHIX) gtLocal += gv;
    }
    __syncthreads();

    // ---- column mask for the central sum ----
    float4 cm;
    cm.x = (col0 + 0 >= CLO && col0 + 0 < CHIX) ? 1.f : 0.f;
    cm.y = (col0 + 1 >= CLO && col0 + 1 < CHIX) ? 1.f : 0.f;
    cm.z = (col0 + 2 >= CLO && col0 + 2 < CHIX) ? 1.f : 0.f;
    cm.w = (col0 + 3 >= CLO && col0 + 3 < CHIX) ? 1.f : 0.f;

    float fnTotal = 0.f;

    #pragma unroll 1
    for (int k = 0; k < 5; ++k) {
        if (k > 0) {
            int p = (k - 1) & 1;
            cTop = ld4(eT + (p * ETSLOT + w) * EXTX + col0);
            cBot = ld4(eB + (p * WARPS + w) * EXTX + col0);
        }
        float4 hP = hsum(cTop);
        float4 cCur = c[0];
        float4 hC = hsum(cCur);
        float iterSum = 0.f;
        const int  pw    = k & 1;
        const bool doUpd = (k < 4);

        #pragma unroll
        for (int r = 0; r < R; ++r) {
            const int y = 1 + w * R + r;
            float4 cN = (r < R - 1) ? c[r + 1] : cBot;
            float4 hN = hsum(cN);

            float4 d;
            d.x = __saturatef(hP.x + hC.x + hN.x);
            d.y = __saturatef(hP.y + hC.y + hN.y);
            d.z = __saturatef(hP.z + hC.z + hN.z);
            d.w = __saturatef(hP.w + hC.w + hN.w);

            // sigmoid(20(d-p-0.5)) = 0.5 + 0.5*tanh(10d - 10p - 5)
            float4 th;
            th.x = tanha(fmaf(d.x, 10.f, fmaf(cCur.x, -10.f, -5.f)));
            th.y = tanha(fmaf(d.y, 10.f, fmaf(cCur.y, -10.f, -5.f)));
            th.z = tanha(fmaf(d.z, 10.f, fmaf(cCur.z, -10.f, -5.f)));
            th.w = tanha(fmaf(d.w, 10.f, fmaf(cCur.w, -10.f, -5.f)));

            float4 g2 = ld4(gtb + y * EXTX + col0);      // gt/2
            float4 fn;                                    // gt * sigmoid
            fn.x = fmaf(g2.x, th.x, g2.x);
            fn.y = fmaf(g2.y, th.y, g2.y);
            fn.z = fmaf(g2.z, th.z, g2.z);
            fn.w = fmaf(g2.w, th.w, g2.w);

            if (doUpd) {
                float4 np;
                np.x = cCur.x + fn.x;
                np.y = cCur.y + fn.y;
                np.z = cCur.z + fn.z;
                np.w = cCur.w + fn.w;
                c[r] = np;
                if (r == 0 && w > 0)
                    st4(eB + (pw * WARPS + (w - 1)) * EXTX + col0, np);
                if (r == R - 1)
                    st4(eT + (pw * ETSLOT + (w + 1)) * EXTX + col0, np);
            }

            if (y >= CLO && y < CHIY) {
                iterSum = fmaf(fn.x, cm.x, iterSum);
                iterSum = fmaf(fn.y, cm.y, iterSum);
                iterSum = fmaf(fn.z, cm.z, iterSum);
                iterSum = fmaf(fn.w, cm.w, iterSum);
            }

            hP = hC; hC = hN; cCur = cN;
        }

        const float wk = (float)((k + 1) * (k + 1));
        fnTotal = fmaf(wk, iterSum, fnTotal);
        __syncthreads();
    }

    // ---- block reduction -> global atomics, last block finalizes ----
    #pragma unroll
    for (int o = 16; o; o >>= 1) {
        fnTotal += __shfl_down_sync(0xffffffffu, fnTotal, o);
        gtLocal += __shfl_down_sync(0xffffffffu, gtLocal, o);
    }
    __shared__ float red[WARPS][2];
    if (lane == 0) { red[w][0] = fnTotal; red[w][1] = gtLocal; }
    __syncthreads();
    if (tid < 32) {
        fnTotal = (tid < WARPS) ? red[tid][0] : 0.f;
        gtLocal = (tid < WARPS) ? red[tid][1] : 0.f;
        #pragma unroll
        for (int o = 4; o; o >>= 1) {
            fnTotal += __shfl_down_sync(0xffffffffu, fnTotal, o);
            gtLocal += __shfl_down_sync(0xffffffffu, gtLocal, o);
        }
        if (tid == 0) {
            atomicAdd(&g_acc[0], fnTotal);
            atomicAdd(&g_acc[1], gtLocal);
            __threadfence();
            unsigned prev = atomicAdd(&g_done, 1u);
            if (prev == NBLK - 1) {
                out[0] = g_acc[0] / g_acc[1];
                g_acc[0] = 0.f;
                g_acc[1] = 0.f;
                __threadfence();
                g_done = 0u;
            }
        }
    }
}

extern "C" void kernel_launch(void* const* d_in, const int* in_sizes, int n_in,
                              void* d_out, int out_size)
{
    const float* pred = (const float*)d_in[0];
    const float* gt   = (const float*)d_in[1];

    cudaFuncSetAttribute(wlc_main, cudaFuncAttributeMaxDynamicSharedMemorySize,
                         SMEMB);

    dim3 grid(GRIDX, GRIDY);     // 35 x 74 = 2590 blocks
    wlc_main<<<grid, NT, SMEMB>>>(pred, gt, (float*)d_out);
}

// round 9
// speedup vs baseline: 1.0017x; 1.0017x over previous
#include <cuda_runtime.h>

// WLC loss: fused 5-iter morphological recurrence, register-resident pred.
// NT=256 (8 warps), 3 CTAs/SM (85 regs/thread). Warp = 128-px row band,
// thread owns R=8 rows x 4 cols in registers across all iterations.
// Horizontal neighbors via shfl; vertical warp-strip coupling via small
// double-buffered smem edge rows. pred loaded gmem->regs directly.

#define IMG    4096
#define NT     256
#define WARPS  8
#define R      8
#define EXTX   128
#define TSX    118
#define EXTY   (WARPS * R + 2)     // 66
#define TSY    (EXTY - 10)         // 56
#define GRIDX  35                  // ceil(4096/118)
#define GRIDY  74                  // ceil(4096/56)
#define NBLK   (GRIDX * GRIDY)     // 2590
#define CLO    5
#define CHIX   123                 // useful cols [5,123)
#define CHIY   (EXTY - 5)          // useful rows [5,61)

#define GTN    (EXTY * EXTX)           // 8448 floats (gt/2)
#define ETSLOT (WARPS + 1)
#define ETN    (2 * ETSLOT * EXTX)     // 2304
#define EBN    (2 * WARPS * EXTX)      // 2048
#define SMEMB  ((GTN + ETN + EBN) * 4) // 51200 B

__device__ float    g_acc[2];   // zero-init; self-resets every launch
__device__ unsigned g_done;

__device__ __forceinline__ float tanha(float x) {
    float y; asm("tanh.approx.f32 %0, %1;" : "=f"(y) : "f"(x)); return y;
}
__device__ __forceinline__ float4 ld4(const float* p) {
    return *reinterpret_cast<const float4*>(p);
}
__device__ __forceinline__ void st4(float* p, float4 v) {
    *reinterpret_cast<float4*>(p) = v;
}

// horizontal 3-sums; lane-boundary garbage lands only in the halo-creep zone
__device__ __forceinline__ float4 hsum(float4 c) {
    float l = __shfl_up_sync(0xffffffffu, c.w, 1);
    float r = __shfl_down_sync(0xffffffffu, c.x, 1);
    float t1 = c.x + c.y;
    float t2 = c.z + c.w;
    float4 h;
    h.x = l + t1;
    h.y = t1 + c.z;
    h.z = c.y + t2;
    h.w = t2 + r;
    return h;
}

__device__ __forceinline__ float4 load_pred_row(
    const float* __restrict__ pred, int gy, int gxBase,
    bool c0, bool c1, bool c2, bool c3)
{
    float4 v = make_float4(0.f, 0.f, 0.f, 0.f);
    if ((unsigned)gy < (unsigned)IMG) {
        const float* p = pred + gy * IMG + gxBase;
        if (c0) v.x = __ldg(p + 0);
        if (c1) v.y = __ldg(p + 1);
        if (c2) v.z = __ldg(p + 2);
        if (c3) v.w = __ldg(p + 3);
    }
    return v;
}

__global__ __launch_bounds__(NT, 3)
void wlc_main(const float* __restrict__ pred, const float* __restrict__ gt,
              float* __restrict__ out)
{
    extern __shared__ float sm[];
    float* gtb = sm;             // gt/2 tile [EXTY][EXTX]
    float* eT  = sm + GTN;       // [2][WARPS+1][EXTX] top-edge sources
    float* eB  = eT + ETN;       // [2][WARPS][EXTX]   bottom-edge sources

    const int tid  = threadIdx.x;
    const int w    = tid >> 5;
    const int lane = tid & 31;
    const int col0 = 4 * lane;
    const int gx0  = blockIdx.x * TSX - 5;
    const int gy0  = blockIdx.y * TSY - 5;
    const int gxBase = gx0 + col0;

    const bool c0 = (unsigned)(gxBase + 0) < (unsigned)IMG;
    const bool c1 = (unsigned)(gxBase + 1) < (unsigned)IMG;
    const bool c2 = (unsigned)(gxBase + 2) < (unsigned)IMG;
    const bool c3 = (unsigned)(gxBase + 3) < (unsigned)IMG;

    // ---- pred directly into registers (high MLP, coalesced per warp) ----
    float4 c[R], cTop, cBot;
    cTop = load_pred_row(pred, gy0 + w * R,         gxBase, c0, c1, c2, c3);
    #pragma unroll
    for (int r = 0; r < R; ++r)
        c[r] = load_pred_row(pred, gy0 + 1 + w * R + r, gxBase, c0, c1, c2, c3);
    cBot = load_pred_row(pred, gy0 + 1 + (w + 1) * R,  gxBase, c0, c1, c2, c3);

    // ---- constant edge rows (row 0 / row EXTY-1 of pred_0), both parities ----
    {
        int j   = tid & 127;
        int row = (tid < 128) ? 0 : (EXTY - 1);
        int gy  = gy0 + row, gx = gx0 + j;
        float v = 0.f;
        if (((unsigned)gy < (unsigned)IMG) & ((unsigned)gx < (unsigned)IMG))
            v = __ldg(pred + gy * IMG + gx);
        if (tid < 128) {
            eT[0 * ETSLOT * EXTX + j] = v;
            eT[1 * ETSLOT * EXTX + j] = v;
        } else {
            eB[(0 * WARPS + WARPS - 1) * EXTX + j] = v;
            eB[(1 * WARPS + WARPS - 1) * EXTX + j] = v;
        }
    }

    // ---- gt: store gt/2 into smem, accumulate central gt sum ----
    float gtLocal = 0.f;
    #pragma unroll 1
    for (int i = tid; i < GTN; i += NT) {
        int r = i >> 7, cc = i & 127;
        int gy = gy0 + r, gx = gx0 + cc;
        float gv = 0.f;
        if (((unsigned)gy < (unsigned)IMG) & ((unsigned)gx < (unsigned)IMG))
            gv = __ldg(gt + gy * IMG + gx);
        gtb[i] = 0.5f * gv;
        if (r >= CLO && r < CHIY && cc >= CLO && cc < CHIX) gtLocal += gv;
    }
    __syncthreads();

    // ---- column mask for the central sum ----
    float4 cm;
    cm.x = (col0 + 0 >= CLO && col0 + 0 < CHIX) ? 1.f : 0.f;
    cm.y = (col0 + 1 >= CLO && col0 + 1 < CHIX) ? 1.f : 0.f;
    cm.z = (col0 + 2 >= CLO && col0 + 2 < CHIX) ? 1.f : 0.f;
    cm.w = (col0 + 3 >= CLO && col0 + 3 < CHIX) ? 1.f : 0.f;

    float fnTotal = 0.f;

    #pragma unroll 1
    for (int k = 0; k < 5; ++k) {
        if (k > 0) {
            int p = (k - 1) & 1;
            cTop = ld4(eT + (p * ETSLOT + w) * EXTX + col0);
            cBot = ld4(eB + (p * WARPS + w) * EXTX + col0);
        }
        float4 hP = hsum(cTop);
        float4 cCur = c[0];
        float4 hC = hsum(cCur);
        float iterSum = 0.f;
        const int  pw    = k & 1;
        const bool doUpd = (k < 4);

        #pragma unroll
        for (int r = 0; r < R; ++r) {
            const int y = 1 + w * R + r;
            float4 cN = (r < R - 1) ? c[r + 1] : cBot;
            float4 hN = hsum(cN);

            float4 d;
            d.x = __saturatef(hP.x + hC.x + hN.x);
            d.y = __saturatef(hP.y + hC.y + hN.y);
            d.z = __saturatef(hP.z + hC.z + hN.z);
            d.w = __saturatef(hP.w + hC.w + hN.w);

            // sigmoid(20(d-p-0.5)) = 0.5 + 0.5*tanh(10d - 10p - 5)
            float4 th;
            th.x = tanha(fmaf(d.x, 10.f, fmaf(cCur.x, -10.f, -5.f)));
            th.y = tanha(fmaf(d.y, 10.f, fmaf(cCur.y, -10.f, -5.f)));
            th.z = tanha(fmaf(d.z, 10.f, fmaf(cCur.z, -10.f, -5.f)));
            th.w = tanha(fmaf(d.w, 10.f, fmaf(cCur.w, -10.f, -5.f)));

            float4 g2 = ld4(gtb + y * EXTX + col0);      // gt/2
            float4 fn;                                    // gt * sigmoid
            fn.x = fmaf(g2.x, th.x, g2.x);
            fn.y = fmaf(g2.y, th.y, g2.y);
            fn.z = fmaf(g2.z, th.z, g2.z);
            fn.w = fmaf(g2.w, th.w, g2.w);

            if (doUpd) {
                float4 np;
                np.x = cCur.x + fn.x;
                np.y = cCur.y + fn.y;
                np.z = cCur.z + fn.z;
                np.w = cCur.w + fn.w;
                c[r] = np;
                if (r == 0 && w > 0)
                    st4(eB + (pw * WARPS + (w - 1)) * EXTX + col0, np);
                if (r == R - 1)
                    st4(eT + (pw * ETSLOT + (w + 1)) * EXTX + col0, np);
            }

            if (y >= CLO && y < CHIY) {
                iterSum = fmaf(fn.x, cm.x, iterSum);
                iterSum = fmaf(fn.y, cm.y, iterSum);
                iterSum = fmaf(fn.z, cm.z, iterSum);
                iterSum = fmaf(fn.w, cm.w, iterSum);
            }

            hP = hC; hC = hN; cCur = cN;
        }

        const float wk = (float)((k + 1) * (k + 1));
        fnTotal = fmaf(wk, iterSum, fnTotal);
        __syncthreads();
    }

    // ---- block reduction -> global atomics, last block finalizes ----
    #pragma unroll
    for (int o = 16; o; o >>= 1) {
        fnTotal += __shfl_down_sync(0xffffffffu, fnTotal, o);
        gtLocal += __shfl_down_sync(0xffffffffu, gtLocal, o);
    }
    __shared__ float red[WARPS][2];
    if (lane == 0) { red[w][0] = fnTotal; red[w][1] = gtLocal; }
    __syncthreads();
    if (tid < 32) {
        fnTotal = (tid < WARPS) ? red[tid][0] : 0.f;
        gtLocal = (tid < WARPS) ? red[tid][1] : 0.f;
        #pragma unroll
        for (int o = 4; o; o >>= 1) {
            fnTotal += __shfl_down_sync(0xffffffffu, fnTotal, o);
            gtLocal += __shfl_down_sync(0xffffffffu, gtLocal, o);
        }
        if (tid == 0) {
            atomicAdd(&g_acc[0], fnTotal);
            atomicAdd(&g_acc[1], gtLocal);
            __threadfence();
            unsigned prev = atomicAdd(&g_done, 1u);
            if (prev == NBLK - 1) {
                out[0] = g_acc[0] / g_acc[1];
                g_acc[0] = 0.f;
                g_acc[1] = 0.f;
                __threadfence();
                g_done = 0u;
            }
        }
    }
}

extern "C" void kernel_launch(void* const* d_in, const int* in_sizes, int n_in,
                              void* d_out, int out_size)
{
    const float* pred = (const float*)d_in[0];
    const float* gt   = (const float*)d_in[1];

    cudaFuncSetAttribute(wlc_main, cudaFuncAttributeMaxDynamicSharedMemorySize,
                         SMEMB);

    dim3 grid(GRIDX, GRIDY);     // 35 x 74 = 2590 blocks
    wlc_main<<<grid, NT, SMEMB>>>(pred, gt, (float*)d_out);
}

// round 12
// speedup vs baseline: 1.7303x; 1.7274x over previous
#include <cuda_runtime.h>

// WLC loss: fused 5-iter morphological recurrence, register-resident pred,
// packed f32x2 arithmetic. Warp = 128-px row band (32 lanes x 4 cols),
// thread owns R=8 rows across all iterations; warp strips exchange edge rows
// via double-buffered smem. TSX=112 with left-halo 8 => 16B-aligned LDG.128.

#define IMG    4096
#define NT     448
#define WARPS  14
#define R      8
#define EXTX   128
#define TSX    112                 // useful width; gx0 = bx*112-8 aligned
#define EXTY   (WARPS * R + 2)     // 114
#define TSY    (EXTY - 10)         // 104
#define GRIDX  37                  // ceil(4096/112)
#define GRIDY  40                  // ceil(4096/104)
#define NBLK   (GRIDX * GRIDY)     // 1480
#define CLOX   8                   // useful ext cols [8,120)
#define CHIX   120
#define CLOY   5                   // useful ext rows [5,109)
#define CHIY   (EXTY - 5)

#define GTN    (EXTY * EXTX)           // 14592 floats (gt/2)
#define ETSLOT (WARPS + 1)
#define ETN    (2 * ETSLOT * EXTX)     // 3840
#define EBN    (2 * WARPS * EXTX)      // 3584
#define SMEMB  ((GTN + ETN + EBN) * 4) // 88064 B

typedef unsigned long long ull;

__device__ float    g_acc[2];   // zero-init; self-resets every launch
__device__ unsigned g_done;

__device__ __forceinline__ float tanha(float x) {
    float y; asm("tanh.approx.f32 %0, %1;" : "=f"(y) : "f"(x)); return y;
}
__device__ __forceinline__ ull pk2(float a, float b) {
    ull r; asm("mov.b64 %0, {%1, %2};" : "=l"(r) : "f"(a), "f"(b)); return r;
}
__device__ __forceinline__ void up2(ull v, float& a, float& b) {
    asm("mov.b64 {%0, %1}, %2;" : "=f"(a), "=f"(b) : "l"(v));
}
__device__ __forceinline__ ull add2(ull a, ull b) {
    ull r; asm("add.rn.f32x2 %0, %1, %2;" : "=l"(r) : "l"(a), "l"(b)); return r;
}
__device__ __forceinline__ ull fma2(ull a, ull b, ull c) {
    ull r; asm("fma.rn.f32x2 %0, %1, %2, %3;" : "=l"(r) : "l"(a), "l"(b), "l"(c));
    return r;
}

struct F2x2 { ull a, b; };   // (x,y),(z,w)

// horizontal 3-sums; lane-boundary values only pollute the halo-creep zone
__device__ __forceinline__ F2x2 hsum2(F2x2 v) {
    float x, y, z, w;
    up2(v.a, x, y); up2(v.b, z, w);
    float l = __shfl_up_sync(0xffffffffu, w, 1);
    float r = __shfl_down_sync(0xffffffffu, x, 1);
    float t1 = x + y, t2 = z + w;
    F2x2 h;
    h.a = pk2(l + t1, t1 + z);
    h.b = pk2(y + t2, t2 + r);
    return h;
}

__device__ __forceinline__ float4 ldrow(const float* __restrict__ p, int gy, int gx) {
    if (((unsigned)gy < (unsigned)IMG) && ((unsigned)gx <= (unsigned)(IMG - 4)))
        return *reinterpret_cast<const float4*>(p + (size_t)gy * IMG + gx);
    return make_float4(0.f, 0.f, 0.f, 0.f);
}

__global__ __launch_bounds__(NT, 2)
void wlc_main(const float* __restrict__ pred, const float* __restrict__ gt,
              float* __restrict__ out)
{
    extern __shared__ float sm[];
    float* gtb = sm;             // gt/2 tile [EXTY][EXTX]
    float* eT  = sm + GTN;       // [2][WARPS+1][EXTX]
    float* eB  = eT + ETN;       // [2][WARPS][EXTX]

    const int tid  = threadIdx.x;
    const int w    = tid >> 5;
    const int lane = tid & 31;
    const int col0 = 4 * lane;
    const int gx0  = blockIdx.x * TSX - CLOX;   // aligned to 4
    const int gy0  = blockIdx.y * TSY - CLOY;
    const int gxB  = gx0 + col0;

    // ---- pred rows straight into registers (LDG.128, all-or-nothing) ----
    F2x2 c[R], cTop, cBot;
    {
        float4 v = ldrow(pred, gy0 + w * R, gxB);
        cTop.a = pk2(v.x, v.y); cTop.b = pk2(v.z, v.w);
        #pragma unroll
        for (int r = 0; r < R; ++r) {
            v = ldrow(pred, gy0 + 1 + w * R + r, gxB);
            c[r].a = pk2(v.x, v.y); c[r].b = pk2(v.z, v.w);
        }
        v = ldrow(pred, gy0 + 1 + (w + 1) * R, gxB);
        cBot.a = pk2(v.x, v.y); cBot.b = pk2(v.z, v.w);
    }

    // ---- constant edge rows (pred_0 rows 0 / EXTY-1), both parities ----
    if (tid < 2 * EXTX) {
        int j   = tid & 127;
        int row = (tid < EXTX) ? 0 : (EXTY - 1);
        int gy  = gy0 + row, gx = gx0 + j;
        float v = 0.f;
        if (((unsigned)gy < (unsigned)IMG) & ((unsigned)gx < (unsigned)IMG))
            v = __ldg(pred + (size_t)gy * IMG + gx);
        if (tid < EXTX) {
            eT[0 * ETSLOT * EXTX + j] = v;
            eT[1 * ETSLOT * EXTX + j] = v;
        } else {
            eB[(0 * WARPS + WARPS - 1) * EXTX + j] = v;
            eB[(1 * WARPS + WARPS - 1) * EXTX + j] = v;
        }
    }

    // ---- gt: vectorized load, store gt/2, central sum ----
    float gtLocal = 0.f;
    #pragma unroll 1
    for (int i = tid; i < GTN / 4; i += NT) {
        int r  = i >> 5;             // 32 float4 per row
        int c4 = (i & 31) << 2;
        float4 v = ldrow(gt, gy0 + r, gx0 + c4);
        float4 h; h.x = 0.5f * v.x; h.y = 0.5f * v.y; h.z = 0.5f * v.z; h.w = 0.5f * v.w;
        *reinterpret_cast<float4*>(gtb + r * EXTX + c4) = h;
        if (r >= CLOY && r < CHIY && c4 >= CLOX && c4 < CHIX)
            gtLocal += (v.x + v.y) + (v.z + v.w);
    }
    __syncthreads();

    const bool colIn = (col0 >= CLOX) && (col0 < CHIX);   // whole-quad in/out
    const ull K10  = pk2(10.f, 10.f);
    const ull KN10 = pk2(-10.f, -10.f);
    const ull KN5  = pk2(-5.f, -5.f);

    ull fnTotA = pk2(0.f, 0.f), fnTotB = fnTotA;

    #pragma unroll 1
    for (int k = 0; k < 5; ++k) {
        if (k > 0) {
            int p = (k - 1) & 1;
            float4 v = *reinterpret_cast<const float4*>(eT + (p * ETSLOT + w) * EXTX + col0);
            cTop.a = pk2(v.x, v.y); cTop.b = pk2(v.z, v.w);
            v = *reinterpret_cast<const float4*>(eB + (p * WARPS + w) * EXTX + col0);
            cBot.a = pk2(v.x, v.y); cBot.b = pk2(v.z, v.w);
        }
        F2x2 hP = hsum2(cTop);
        F2x2 cC = c[0];
        F2x2 hC = hsum2(cC);
        ull accA = pk2(0.f, 0.f), accB = accA;
        const int  pw    = k & 1;
        const bool doUpd = (k < 4);

        #pragma unroll
        for (int r = 0; r < R; ++r) {
            const int y = 1 + w * R + r;
            F2x2 cN = (r < R - 1) ? c[r + 1] : cBot;
            F2x2 hN = hsum2(cN);

            ull sA = add2(add2(hP.a, hC.a), hN.a);     // unsat vertical sum
            ull sB = add2(add2(hP.b, hC.b), hN.b);
            ull mA = fma2(cC.a, KN10, KN5);            // -10c - 5
            ull mB = fma2(cC.b, KN10, KN5);
            ull a1A = fma2(sA, K10, mA);               // 10s + m
            ull a1B = fma2(sB, K10, mB);
            ull a2A = add2(mA, K10);                   // 10 + m  (clip at d=1)
            ull a2B = add2(mB, K10);

            float p0, p1, p2, p3, q0, q1, q2, q3;
            up2(a1A, p0, p1); up2(a1B, p2, p3);
            up2(a2A, q0, q1); up2(a2B, q2, q3);
            ull thA = pk2(tanha(fminf(p0, q0)), tanha(fminf(p1, q1)));
            ull thB = pk2(tanha(fminf(p2, q2)), tanha(fminf(p3, q3)));

            float4 g4 = *reinterpret_cast<const float4*>(gtb + y * EXTX + col0);
            ull gA = pk2(g4.x, g4.y), gB = pk2(g4.z, g4.w);
            ull fnA = fma2(gA, thA, gA);               // gt * sigmoid
            ull fnB = fma2(gB, thB, gB);

            if (doUpd) {
                F2x2 np;
                np.a = add2(cC.a, fnA);
                np.b = add2(cC.b, fnB);
                c[r] = np;
                if (r == 0 && w > 0) {
                    ull* e = reinterpret_cast<ull*>(eB + (pw * WARPS + (w - 1)) * EXTX + col0);
                    e[0] = np.a; e[1] = np.b;
                }
                if (r == R - 1) {
                    ull* e = reinterpret_cast<ull*>(eT + (pw * ETSLOT + (w + 1)) * EXTX + col0);
                    e[0] = np.a; e[1] = np.b;
                }
            }

            if (colIn && y >= CLOY && y < CHIY) {
                accA = add2(accA, fnA);
                accB = add2(accB, fnB);
            }

            hP = hC; hC = hN; cC = cN;
        }

        const float wk = (float)((k + 1) * (k + 1));
        const ull wkp = pk2(wk, wk);
        fnTotA = fma2(accA, wkp, fnTotA);
        fnTotB = fma2(accB, wkp, fnTotB);
        __syncthreads();
    }

    // ---- horizontal collapse of packed accumulator ----
    float u0, u1, u2, u3;
    up2(fnTotA, u0, u1); up2(fnTotB, u2, u3);
    float fnTotal = (u0 + u1) + (u2 + u3);

    // ---- block reduction -> global atomics, last block finalizes ----
    #pragma unroll
    for (int o = 16; o; o >>= 1) {
        fnTotal += __shfl_down_sync(0xffffffffu, fnTotal, o);
        gtLocal += __shfl_down_sync(0xffffffffu, gtLocal, o);
    }
    __shared__ float red[WARPS][2];
    if (lane == 0) { red[w][0] = fnTotal; red[w][1] = gtLocal; }
    __syncthreads();
    if (tid < 32) {
        fnTotal = (tid < WARPS) ? red[tid][0] : 0.f;
        gtLocal = (tid < WARPS) ? red[tid][1] : 0.f;
        #pragma unroll
        for (int o = 8; o; o >>= 1) {
            fnTotal += __shfl_down_sync(0xffffffffu, fnTotal, o);
            gtLocal += __shfl_down_sync(0xffffffffu, gtLocal, o);
        }
        if (tid == 0) {
            atomicAdd(&g_acc[0], fnTotal);
            atomicAdd(&g_acc[1], gtLocal);
            __threadfence();
            unsigned prev = atomicAdd(&g_done, 1u);
            if (prev == NBLK - 1) {
                out[0] = g_acc[0] / g_acc[1];
                g_acc[0] = 0.f;
                g_acc[1] = 0.f;
                __threadfence();
                g_done = 0u;
            }
        }
    }
}

extern "C" void kernel_launch(void* const* d_in, const int* in_sizes, int n_in,
                              void* d_out, int out_size)
{
    const float* pred = (const float*)d_in[0];
    const float* gt   = (const float*)d_in[1];

    cudaFuncSetAttribute(wlc_main, cudaFuncAttributeMaxDynamicSharedMemorySize,
                         SMEMB);

    dim3 grid(GRIDX, GRIDY);     // 37 x 40 = 1480 blocks
    wlc_main<<<grid, NT, SMEMB>>>(pred, gt, (float*)d_out);
}

// round 14
// speedup vs baseline: 1.7760x; 1.0264x over previous
#include <cuda_runtime.h>

// WLC loss: fused 5-iter morphological recurrence, register-resident pred,
// packed f32x2 arithmetic. Warp = 128-px row band (32 lanes x 4 cols),
// thread owns R=7 rows; warp strips exchange edge rows via double-buffered
// smem. NT=512, 2 CTAs/SM @ 64 regs => 32 warps/SM.

#define IMG    4096
#define NT     512
#define WARPS  16
#define R      7
#define EXTX   128
#define TSX    112                 // gx0 = bx*112-8 => 16B-aligned
#define EXTY   (WARPS * R + 2)     // 114
#define TSY    (EXTY - 10)         // 104
#define GRIDX  37                  // ceil(4096/112)
#define GRIDY  40                  // ceil(4096/104)
#define NBLK   (GRIDX * GRIDY)     // 1480 = 5.0 waves of 296
#define CLOX   8                   // useful ext cols [8,120)
#define CHIX   120
#define CLOY   5                   // useful ext rows [5,109)
#define CHIY   (EXTY - 5)

#define GTN    (EXTY * EXTX)           // 14592 floats (gt/2)
#define ETSLOT (WARPS + 1)
#define ETN    (2 * ETSLOT * EXTX)     // 4352
#define EBN    (2 * WARPS * EXTX)      // 4096
#define SMEMB  ((GTN + ETN + EBN) * 4) // 92160 B (2 CTAs fit in 228KB)

typedef unsigned long long ull;

__device__ float    g_acc[2];   // zero-init; self-resets every launch
__device__ unsigned g_done;

__device__ __forceinline__ float tanha(float x) {
    float y; asm("tanh.approx.f32 %0, %1;" : "=f"(y) : "f"(x)); return y;
}
__device__ __forceinline__ ull pk2(float a, float b) {
    ull r; asm("mov.b64 %0, {%1, %2};" : "=l"(r) : "f"(a), "f"(b)); return r;
}
__device__ __forceinline__ void up2(ull v, float& a, float& b) {
    asm("mov.b64 {%0, %1}, %2;" : "=f"(a), "=f"(b) : "l"(v));
}
__device__ __forceinline__ ull add2(ull a, ull b) {
    ull r; asm("add.rn.f32x2 %0, %1, %2;" : "=l"(r) : "l"(a), "l"(b)); return r;
}
__device__ __forceinline__ ull fma2(ull a, ull b, ull c) {
    ull r; asm("fma.rn.f32x2 %0, %1, %2, %3;" : "=l"(r) : "l"(a), "l"(b), "l"(c));
    return r;
}

struct F2x2 { ull a, b; };   // (x,y),(z,w)

// horizontal 3-sums; lane-boundary values only pollute the halo-creep zone
__device__ __forceinline__ F2x2 hsum2(F2x2 v) {
    float x, y, z, w;
    up2(v.a, x, y); up2(v.b, z, w);
    float l = __shfl_up_sync(0xffffffffu, w, 1);
    float r = __shfl_down_sync(0xffffffffu, x, 1);
    float t1 = x + y, t2 = z + w;
    F2x2 h;
    h.a = pk2(l + t1, t1 + z);
    h.b = pk2(y + t2, t2 + r);
    return h;
}

__device__ __forceinline__ float4 ldrow(const float* __restrict__ p, int gy, int gx) {
    if (((unsigned)gy < (unsigned)IMG) && ((unsigned)gx <= (unsigned)(IMG - 4)))
        return *reinterpret_cast<const float4*>(p + (size_t)gy * IMG + gx);
    return make_float4(0.f, 0.f, 0.f, 0.f);
}

__global__ __launch_bounds__(NT, 2)
void wlc_main(const float* __restrict__ pred, const float* __restrict__ gt,
              float* __restrict__ out)
{
    extern __shared__ float sm[];
    float* gtb = sm;             // gt/2 tile [EXTY][EXTX]
    float* eT  = sm + GTN;       // [2][WARPS+1][EXTX]
    float* eB  = eT + ETN;       // [2][WARPS][EXTX]

    const int tid  = threadIdx.x;
    const int w    = tid >> 5;
    const int lane = tid & 31;
    const int col0 = 4 * lane;
    const int gx0  = blockIdx.x * TSX - CLOX;   // aligned to 4
    const int gy0  = blockIdx.y * TSY - CLOY;
    const int gxB  = gx0 + col0;

    // ---- pred rows straight into registers (LDG.128, all-or-nothing) ----
    F2x2 c[R], cBot;
    ull  topA, topB;     // cTop held only until first hsum
    {
        float4 v = ldrow(pred, gy0 + w * R, gxB);
        topA = pk2(v.x, v.y); topB = pk2(v.z, v.w);
        #pragma unroll
        for (int r = 0; r < R; ++r) {
            v = ldrow(pred, gy0 + 1 + w * R + r, gxB);
            c[r].a = pk2(v.x, v.y); c[r].b = pk2(v.z, v.w);
        }
        v = ldrow(pred, gy0 + 1 + (w + 1) * R, gxB);
        cBot.a = pk2(v.x, v.y); cBot.b = pk2(v.z, v.w);
    }

    // ---- constant edge rows (pred_0 rows 0 / EXTY-1), both parities ----
    if (tid < 2 * EXTX) {
        int j   = tid & 127;
        int row = (tid < EXTX) ? 0 : (EXTY - 1);
        int gy  = gy0 + row, gx = gx0 + j;
        float v = 0.f;
        if (((unsigned)gy < (unsigned)IMG) & ((unsigned)gx < (unsigned)IMG))
            v = __ldg(pred + (size_t)gy * IMG + gx);
        if (tid < EXTX) {
            eT[0 * ETSLOT * EXTX + j] = v;
            eT[1 * ETSLOT * EXTX + j] = v;
        } else {
            eB[(0 * WARPS + WARPS - 1) * EXTX + j] = v;
            eB[(1 * WARPS + WARPS - 1) * EXTX + j] = v;
        }
    }

    // ---- gt: vectorized load, store gt/2, central sum ----
    float gtLocal = 0.f;
    #pragma unroll 1
    for (int i = tid; i < GTN / 4; i += NT) {
        int r  = i >> 5;             // 32 float4 per row
        int c4 = (i & 31) << 2;
        float4 v = ldrow(gt, gy0 + r, gx0 + c4);
        float4 h; h.x = 0.5f * v.x; h.y = 0.5f * v.y; h.z = 0.5f * v.z; h.w = 0.5f * v.w;
        *reinterpret_cast<float4*>(gtb + r * EXTX + c4) = h;
        if (r >= CLOY && r < CHIY && c4 >= CLOX && c4 < CHIX)
            gtLocal += (v.x + v.y) + (v.z + v.w);
    }
    __syncthreads();

    const bool colIn = (col0 >= CLOX) && (col0 < CHIX);   // whole-quad in/out
    const ull K10  = pk2(10.f, 10.f);
    const ull KN10 = pk2(-10.f, -10.f);
    const ull KN5  = pk2(-5.f, -5.f);

    ull fnTot = pk2(0.f, 0.f);

    #pragma unroll 1
    for (int k = 0; k < 5; ++k) {
        if (k > 0) {
            int p = (k - 1) & 1;
            float4 v = *reinterpret_cast<const float4*>(eT + (p * ETSLOT + w) * EXTX + col0);
            topA = pk2(v.x, v.y); topB = pk2(v.z, v.w);
            v = *reinterpret_cast<const float4*>(eB + (p * WARPS + w) * EXTX + col0);
            cBot.a = pk2(v.x, v.y); cBot.b = pk2(v.z, v.w);
        }
        F2x2 cT; cT.a = topA; cT.b = topB;
        F2x2 hP = hsum2(cT);
        F2x2 cC = c[0];
        F2x2 hC = hsum2(cC);
        ull accA = pk2(0.f, 0.f), accB = accA;
        const int  pw    = k & 1;
        const bool doUpd = (k < 4);

        #pragma unroll
        for (int r = 0; r < R; ++r) {
            const int y = 1 + w * R + r;
            F2x2 cN = (r < R - 1) ? c[r + 1] : cBot;
            F2x2 hN = hsum2(cN);

            ull sA = add2(add2(hP.a, hC.a), hN.a);     // unsat vertical sum
            ull sB = add2(add2(hP.b, hC.b), hN.b);
            ull mA = fma2(cC.a, KN10, KN5);            // -10c - 5
            ull mB = fma2(cC.b, KN10, KN5);
            ull a1A = fma2(sA, K10, mA);               // 10s + m
            ull a1B = fma2(sB, K10, mB);
            ull a2A = add2(mA, K10);                   // 10 + m  (clip at d=1)
            ull a2B = add2(mB, K10);

            float p0, p1, p2, p3, q0, q1, q2, q3;
            up2(a1A, p0, p1); up2(a1B, p2, p3);
            up2(a2A, q0, q1); up2(a2B, q2, q3);
            ull thA = pk2(tanha(fminf(p0, q0)), tanha(fminf(p1, q1)));
            ull thB = pk2(tanha(fminf(p2, q2)), tanha(fminf(p3, q3)));

            float4 g4 = *reinterpret_cast<const float4*>(gtb + y * EXTX + col0);
            ull gA = pk2(g4.x, g4.y), gB = pk2(g4.z, g4.w);
            ull fnA = fma2(gA, thA, gA);               // gt * sigmoid
            ull fnB = fma2(gB, thB, gB);

            if (doUpd) {
                F2x2 np;
                np.a = add2(cC.a, fnA);
                np.b = add2(cC.b, fnB);
                c[r] = np;
                if (r == 0 && w > 0) {
                    ull* e = reinterpret_cast<ull*>(eB + (pw * WARPS + (w - 1)) * EXTX + col0);
                    e[0] = np.a; e[1] = np.b;
                }
                if (r == R - 1) {
                    ull* e = reinterpret_cast<ull*>(eT + (pw * ETSLOT + (w + 1)) * EXTX + col0);
                    e[0] = np.a; e[1] = np.b;
                }
            }

            if (colIn && y >= CLOY && y < CHIY) {
                accA = add2(accA, fnA);
                accB = add2(accB, fnB);
            }

            hP = hC; hC = hN; cC = cN;
        }

        const float wk = (float)((k + 1) * (k + 1));
        const ull wkp = pk2(wk, wk);
        fnTot = fma2(add2(accA, accB), wkp, fnTot);
        __syncthreads();
    }

    // ---- horizontal collapse of packed accumulator ----
    float u0, u1;
    up2(fnTot, u0, u1);
    float fnTotal = u0 + u1;

    // ---- block reduction -> global atomics, last block finalizes ----
    #pragma unroll
    for (int o = 16; o; o >>= 1) {
        fnTotal += __shfl_down_sync(0xffffffffu, fnTotal, o);
        gtLocal += __shfl_down_sync(0xffffffffu, gtLocal, o);
    }
    __shared__ float red[WARPS][2];
    if (lane == 0) { red[w][0] = fnTotal; red[w][1] = gtLocal; }
    __syncthreads();
    if (tid < 32) {
        fnTotal = (tid < WARPS) ? red[tid][0] : 0.f;
        gtLocal = (tid < WARPS) ? red[tid][1] : 0.f;
        #pragma unroll
        for (int o = 8; o; o >>= 1) {
            fnTotal += __shfl_down_sync(0xffffffffu, fnTotal, o);
            gtLocal += __shfl_down_sync(0xffffffffu, gtLocal, o);
        }
        if (tid == 0) {
            atomicAdd(&g_acc[0], fnTotal);
            atomicAdd(&g_acc[1], gtLocal);
            __threadfence();
            unsigned prev = atomicAdd(&g_done, 1u);
            if (prev == NBLK - 1) {
                out[0] = g_acc[0] / g_acc[1];
                g_acc[0] = 0.f;
                g_acc[1] = 0.f;
                __threadfence();
                g_done = 0u;
            }
        }
    }
}

extern "C" void kernel_launch(void* const* d_in, const int* in_sizes, int n_in,
                              void* d_out, int out_size)
{
    const float* pred = (const float*)d_in[0];
    const float* gt   = (const float*)d_in[1];

    cudaFuncSetAttribute(wlc_main, cudaFuncAttributeMaxDynamicSharedMemorySize,
                         SMEMB);

    dim3 grid(GRIDX, GRIDY);     // 37 x 40 = 1480 blocks
    wlc_main<<<grid, NT, SMEMB>>>(pred, gt, (float*)d_out);
}